// round 13
// baseline (speedup 1.0000x reference)
#include <cuda_runtime.h>
#include <cuda_bf16.h>
#include <cstdint>

// ============================================================================
// RNNModel B=262144, F=5, T=4, H=128, L=5 — bf16 mma.sync split-precision v5.
// 3-term split (W=Wh+Wl, h=hh+hl; D = AhBh + AhBl + AlBh), ldmatrix fragment
// loads, 4 batch groups of 4 warps (v3 skeleton). v5 deltas vs v3:
//   - dense (unpadded) weight storage in gmem; contiguous cp.async copy that
//     scatters into the padded SMEM layout (global reads stay fully coalesced)
//   - Whh copy overlapped with the t=0 epilogue only (single commit group)
//   - epilogue/x-staging use packed cvt.rn.bf16x2 (bit-identical rounding)
// (Resubmission: previous round failed in bench infra before any GPU signal.)
// ============================================================================

#define HDIM 128
#define TSEQ 4
#define MB   64
#define NT   512
#define NLAYER 5

#define HPW  68                  // padded row stride in u32 words (136 bf16, 272 B)
#define ROWB 272                 // bytes per padded SMEM row
#define DROWB 256                // bytes per dense gmem row
#define W_HALF_BYTES 34816       // 128*272
#define H_TILE_BYTES 17408       // 64*272

// ---- SMEM byte offsets ----
#define OFF_H     0                       // 4t x (hi 17408 + lo 17408) = 139264
#define H_PAIR    34816
#define OFF_W     139264                  // Whi 34816 + Wlo 34816 = 69632
#define OFF_X     208896                  // 4t x (hi 2048 + lo 2048) = 16384
#define X_PAIR    4096
#define OFF_B2    225280                  // 128 fp32
#define OFF_WFC   225792                  // 128 fp32
#define OFF_SPART 226304                  // 256 fp32
#define SMEM_BYTES 227328

// ---- pre-split DENSE weights: slot 2l = W_ih(l), 2l+1 = W_hh(l) ----
// layout: [j][128] bf16 row-major, no padding (16384 elems = 32 KB each).
__device__ __align__(16) __nv_bfloat16 g_Whi[10][16384];
__device__ __align__(16) __nv_bfloat16 g_Wlo[10][16384];

__device__ __forceinline__ uint32_t smem_u32(const void* p){
    uint32_t a;
    asm("{ .reg .u64 t; cvta.to.shared.u64 t, %1; cvt.u32.u64 %0, t; }"
        : "=r"(a) : "l"(p));
    return a;
}

__device__ __forceinline__ void ldm4(uint32_t* r, uint32_t addr){
    asm volatile("ldmatrix.sync.aligned.m8n8.x4.shared.b16 {%0,%1,%2,%3}, [%4];"
        : "=r"(r[0]), "=r"(r[1]), "=r"(r[2]), "=r"(r[3]) : "r"(addr));
}

__device__ __forceinline__ void mma16816(float* c,
        uint32_t a0, uint32_t a1, uint32_t a2, uint32_t a3,
        uint32_t b0, uint32_t b1){
    asm volatile(
        "mma.sync.aligned.m16n8k16.row.col.f32.bf16.bf16.f32 "
        "{%0,%1,%2,%3}, {%4,%5,%6,%7}, {%8,%9}, {%0,%1,%2,%3};"
        : "+f"(c[0]), "+f"(c[1]), "+f"(c[2]), "+f"(c[3])
        : "r"(a0), "r"(a1), "r"(a2), "r"(a3), "r"(b0), "r"(b1));
}

#define GROUP_BAR(gid) \
    asm volatile("bar.sync %0, %1;" :: "r"((gid) + 1), "r"(128) : "memory")

__device__ __forceinline__ void cp_async16(uint32_t dst, const void* src){
    asm volatile("cp.async.cg.shared.global [%0], [%1], 16;"
                 :: "r"(dst), "l"(src) : "memory");
}
#define CP_COMMIT() asm volatile("cp.async.commit_group;" ::: "memory")
#define CP_WAIT0()  asm volatile("cp.async.wait_group 0;" ::: "memory")

// accurate tanh (~1e-7 abs). NOT tanh.approx (6e-4 would compound over 20 steps).
__device__ __forceinline__ float fast_tanh(float x){
    float ax = fabsf(x);
    float e  = __expf(-2.0f * ax);
    float r  = __fdividef(1.0f - e, 1.0f + e);
    return copysignf(r, x);
}

// ============================================================================
// Prep: split all 10 weight matrices into bf16 hi/lo, DENSE [j][128] rows.
// ============================================================================
__global__ void prep_weights(const float* __restrict__ Wih0,
                             const float* __restrict__ Whh0,
                             const float* __restrict__ WihS,
                             const float* __restrict__ WhhS){
    int slot = blockIdx.x;
    for (int idx = threadIdx.x; idx < 16384; idx += blockDim.x){
        int j = idx >> 7, k = idx & 127;
        float w;
        if (slot == 0)      w = (k < 5) ? Wih0[j*5 + k] : 0.0f;
        else if (slot == 1) w = Whh0[j*128 + k];
        else if (slot & 1)  w = WhhS[((slot>>1)-1)*16384 + j*128 + k];
        else                w = WihS[((slot>>1)-1)*16384 + j*128 + k];
        __nv_bfloat16 hi = __float2bfloat16(w);
        __nv_bfloat16 lo = __float2bfloat16(w - __bfloat162float(hi));
        g_Whi[slot][idx] = hi;
        g_Wlo[slot][idx] = lo;
    }
}

// Async-copy one matrix (hi+lo) dense gmem -> padded SMEM. Global reads are
// fully contiguous (thread i reads chunk i of the dense array); SMEM dst is
// scattered to the 272-byte-stride layout (fine: STS needs no coalescing).
__device__ __forceinline__ void copyW_async(int slot, uint32_t sbW, int tid){
    const char* gh = (const char*)g_Whi[slot];
    const char* gl = (const char*)g_Wlo[slot];
    #pragma unroll
    for (int i = tid; i < 2048; i += NT){
        int row = i >> 4, kc = i & 15;
        uint32_t dst = sbW + row * ROWB + kc * 16;
        cp_async16(dst,                 gh + i*16);
        cp_async16(dst + W_HALF_BYTES,  gl + i*16);
    }
    CP_COMMIT();
}

// one k-chunk of a recurrent chain: load frags, 12 MMAs into ct[16]
__device__ __forceinline__ void chain_kk(float* ct,
        uint32_t whAddr, uint32_t wlAddr, uint32_t hBase,
        uint32_t bOff0, uint32_t bOff1, uint32_t aOff, uint32_t kb){
    uint32_t bh[8], bl[8], ah[4], al[4];
    ldm4(bh,     whAddr + bOff0 + kb);
    ldm4(bh + 4, whAddr + bOff1 + kb);
    ldm4(bl,     wlAddr + bOff0 + kb);
    ldm4(bl + 4, wlAddr + bOff1 + kb);
    ldm4(ah, hBase + aOff + kb);
    ldm4(al, hBase + aOff + kb + H_TILE_BYTES);
    #pragma unroll
    for (int nf = 0; nf < 4; nf++)
        mma16816(ct + nf*4, ah[0],ah[1],ah[2],ah[3], bh[nf*2], bh[nf*2+1]);
    #pragma unroll
    for (int nf = 0; nf < 4; nf++)
        mma16816(ct + nf*4, ah[0],ah[1],ah[2],ah[3], bl[nf*2], bl[nf*2+1]);
    #pragma unroll
    for (int nf = 0; nf < 4; nf++)
        mma16816(ct + nf*4, al[0],al[1],al[2],al[3], bh[nf*2], bh[nf*2+1]);
}

// epilogue for one timestep: tanh, split hi/lo (packed cvt, rn — identical
// rounding to __float2bfloat16), store to h tiles
__device__ __forceinline__ void epi_store(const float* ct,
        uint32_t* hh, uint32_t* hl, int baseW){
    #pragma unroll
    for (int nf = 0; nf < 4; nf++){
        #pragma unroll
        for (int p = 0; p < 2; p++){
            float h0 = fast_tanh(ct[nf*4 + 2*p]);
            float h1 = fast_tanh(ct[nf*4 + 2*p + 1]);
            uint32_t ph;
            asm("cvt.rn.bf16x2.f32 %0, %1, %2;" : "=r"(ph) : "f"(h1), "f"(h0));
            float f0 = __uint_as_float(ph << 16);
            float f1 = __uint_as_float(ph & 0xffff0000u);
            uint32_t pl;
            asm("cvt.rn.bf16x2.f32 %0, %1, %2;" : "=r"(pl) : "f"(h1 - f1), "f"(h0 - f0));
            int widx = baseW + p*(8*HPW) + nf*4;
            hh[widx] = ph;
            hl[widx] = pl;
        }
    }
}

// ============================================================================
__global__ void __launch_bounds__(NT)
rnn_mma(const float* __restrict__ x,
        const float* __restrict__ bih0, const float* __restrict__ bhh0,
        const float* __restrict__ bihS, const float* __restrict__ bhhS,
        const float* __restrict__ Wfc,  const float* __restrict__ bfc,
        float* __restrict__ out, int Btot)
{
    extern __shared__ __align__(16) char smem[];
    const uint32_t sb = smem_u32(smem);
    const int tid  = threadIdx.x;
    const int wid  = tid >> 5, lane = tid & 31;
    const int g    = lane >> 2, c = lane & 3;
    const int grp  = wid >> 2;               // batch group 0..3 (spans all SMSPs)
    const int m0   = grp * 16;               // group's 16 batch rows
    const int n0   = (wid & 3) * 32;         // warp's hidden-col base
    const long long baseb = (long long)blockIdx.x * MB;

    float* b2  = (float*)(smem + OFF_B2);
    float* wfc = (float*)(smem + OFF_WFC);

    // ---- per-lane ldmatrix byte offsets ----
    const int aRow = m0 + (lane & 7) + ((lane >> 3) & 1) * 8;
    const int aK8  = (lane >> 4) * 8;
    const uint32_t aOff = (uint32_t)(aRow * ROWB + aK8 * 2);
    const int bRow = (lane & 7) + (lane >> 4) * 8;
    const int bK8  = ((lane >> 3) & 1) * 8;
    const uint32_t bOff0 = (uint32_t)((n0 + bRow) * ROWB + bK8 * 2);
    const uint32_t bOff1 = (uint32_t)((n0 + 16 + bRow) * ROWB + bK8 * 2);
    const int baseW = (m0 + g) * HPW + (n0 >> 1) + c;   // epilogue store base

    // ---- stage wfc + x tiles (bf16 hi/lo split, [64][8 words]) ----
    if (tid < 128) wfc[tid] = Wfc[tid];
    if (tid < 256){
        int b = tid >> 2, t = tid & 3;
        long long gb = baseb + b;
        float xv[5];
        #pragma unroll
        for (int f = 0; f < 5; f++)
            xv[f] = (gb < Btot) ? x[gb*20 + f*4 + t] : 0.0f;
        uint32_t* xh = (uint32_t*)(smem + OFF_X + t*X_PAIR);
        uint32_t* xl = xh + 512;
        #pragma unroll
        for (int w = 0; w < 8; w++){
            float v0 = (2*w   < 5) ? xv[2*w]   : 0.0f;
            float v1 = (2*w+1 < 5) ? xv[2*w+1] : 0.0f;
            uint32_t ph;
            asm("cvt.rn.bf16x2.f32 %0, %1, %2;" : "=r"(ph) : "f"(v1), "f"(v0));
            float f0 = __uint_as_float(ph << 16);
            float f1 = __uint_as_float(ph & 0xffff0000u);
            uint32_t pl;
            asm("cvt.rn.bf16x2.f32 %0, %1, %2;" : "=r"(pl) : "f"(v1 - f1), "f"(v0 - f0));
            xh[b*8 + w] = ph;
            xl[b*8 + w] = pl;
        }
    }

    float acc[64];                           // [t][nf][4]
    const uint32_t whAddr = sb + OFF_W;
    const uint32_t wlAddr = sb + OFF_W + W_HALF_BYTES;
    const uint32_t* whW = (const uint32_t*)(smem + OFF_W);
    const uint32_t* wlW = whW + (W_HALF_BYTES >> 2);

    #pragma unroll 1
    for (int l = 0; l < NLAYER; l++){
        __syncthreads();                     // prev-layer W reads + h writes ordered
        copyW_async(2*l, sb + OFF_W, tid);
        if (tid < 128)
            b2[tid] = (l == 0) ? bih0[tid] + bhh0[tid]
                               : bihS[(l-1)*128 + tid] + bhhS[(l-1)*128 + tid];
        CP_WAIT0();
        __syncthreads();

        // ---- init acc with bias ----
        #pragma unroll
        for (int nf = 0; nf < 4; nf++){
            float bv0 = b2[n0 + nf*8 + c*2];
            float bv1 = b2[n0 + nf*8 + c*2 + 1];
            #pragma unroll
            for (int t = 0; t < 4; t++){
                float* cc = &acc[(t*4 + nf)*4];
                cc[0] = bv0; cc[1] = bv1; cc[2] = bv0; cc[3] = bv1;
            }
        }

        // ---- pass A: acc[t] += Wih . h_prev[t] (no barriers needed) ----
        if (l == 0){
            // single K=16 step from x tiles (scalar LDS; tiny)
            uint32_t bh[8], bl[8];
            #pragma unroll
            for (int nf = 0; nf < 4; nf++){
                int jw = (n0 + nf*8 + g)*HPW + c;
                bh[nf*2]   = whW[jw]; bh[nf*2+1] = whW[jw + 4];
                bl[nf*2]   = wlW[jw]; bl[nf*2+1] = wlW[jw + 4];
            }
            #pragma unroll
            for (int t = 0; t < 4; t++){
                const uint32_t* xh = (const uint32_t*)(smem + OFF_X + t*X_PAIR);
                const uint32_t* xl = xh + 512;
                int rw = (m0 + g)*8 + c;
                uint32_t ah0 = xh[rw], ah1 = xh[rw + 64];
                uint32_t ah2 = xh[rw + 4], ah3 = xh[rw + 68];
                uint32_t al0 = xl[rw], al1 = xl[rw + 64];
                uint32_t al2 = xl[rw + 4], al3 = xl[rw + 68];
                float* ct = &acc[t*16];
                #pragma unroll
                for (int nf = 0; nf < 4; nf++)
                    mma16816(ct + nf*4, ah0,ah1,ah2,ah3, bh[nf*2], bh[nf*2+1]);
                #pragma unroll
                for (int nf = 0; nf < 4; nf++)
                    mma16816(ct + nf*4, ah0,ah1,ah2,ah3, bl[nf*2], bl[nf*2+1]);
                #pragma unroll
                for (int nf = 0; nf < 4; nf++)
                    mma16816(ct + nf*4, al0,al1,al2,al3, bh[nf*2], bh[nf*2+1]);
            }
        } else {
            #pragma unroll 1
            for (int kk = 0; kk < 8; kk++){
                uint32_t kb = kk * 32;       // 16 bf16 = 32 bytes per k-chunk
                uint32_t bh[8], bl[8];
                ldm4(bh,     whAddr + bOff0 + kb);
                ldm4(bh + 4, whAddr + bOff1 + kb);
                ldm4(bl,     wlAddr + bOff0 + kb);
                ldm4(bl + 4, wlAddr + bOff1 + kb);
                #pragma unroll
                for (int t = 0; t < 4; t++){
                    uint32_t hAddr = sb + OFF_H + t*H_PAIR + aOff + kb;
                    uint32_t ah[4], al[4];
                    ldm4(ah, hAddr);
                    ldm4(al, hAddr + H_TILE_BYTES);
                    float* ct = &acc[t*16];
                    #pragma unroll
                    for (int nf = 0; nf < 4; nf++)
                        mma16816(ct + nf*4, ah[0],ah[1],ah[2],ah[3], bh[nf*2], bh[nf*2+1]);
                    #pragma unroll
                    for (int nf = 0; nf < 4; nf++)
                        mma16816(ct + nf*4, ah[0],ah[1],ah[2],ah[3], bl[nf*2], bl[nf*2+1]);
                    #pragma unroll
                    for (int nf = 0; nf < 4; nf++)
                        mma16816(ct + nf*4, al[0],al[1],al[2],al[3], bh[nf*2], bh[nf*2+1]);
                }
            }
        }

        // ---- swap W region to W_hh(l); overlap copy with t=0 epilogue ----
        __syncthreads();                     // pass-A reads of Wih done
        copyW_async(2*l + 1, sb + OFF_W, tid);

        // t=0 epilogue reads no W: runs under the copy
        {
            uint32_t* hh0 = (uint32_t*)(smem + OFF_H + 0*H_PAIR);
            epi_store(&acc[0], hh0, hh0 + (H_TILE_BYTES >> 2), baseW);
            GROUP_BAR(grp);
        }
        CP_WAIT0();
        __syncthreads();

        // ---- pass B: t = 1..3 sequential; 128-thread group barriers ----
        #pragma unroll 1
        for (int t = 1; t < 4; t++){
            float* ct = &acc[t*16];
            uint32_t hBase = sb + OFF_H + (t-1)*H_PAIR;
            #pragma unroll 1
            for (int kq = 0; kq < 8; kq++)
                chain_kk(ct, whAddr, wlAddr, hBase, bOff0, bOff1, aOff, kq*32);
            uint32_t* hh = (uint32_t*)(smem + OFF_H + t*H_PAIR);
            epi_store(ct, hh, hh + (H_TILE_BYTES >> 2), baseW);
            if (t < 3) GROUP_BAR(grp);
            // t==3: next layer-top __syncthreads (or head's) provides ordering
        }
    }

    __syncthreads();                         // all groups' h[3] complete

    // ---- head: out[b] = dot(h3[b], wfc) + bfc ----
    if (tid < 256){
        int b = tid >> 2, q = tid & 3;
        const uint32_t* hh = (const uint32_t*)(smem + OFF_H + 3*H_PAIR);
        const uint32_t* hl = hh + (H_TILE_BYTES >> 2);
        float s = 0.0f;
        #pragma unroll
        for (int w = 0; w < 16; w++){
            int widx = b*HPW + q*16 + w;
            uint32_t uh = hh[widx], ul = hl[widx];
            __nv_bfloat162 vh = *(__nv_bfloat162*)&uh;
            __nv_bfloat162 vl = *(__nv_bfloat162*)&ul;
            int j = q*32 + 2*w;
            s = fmaf(__bfloat162float(vh.x) + __bfloat162float(vl.x), wfc[j],   s);
            s = fmaf(__bfloat162float(vh.y) + __bfloat162float(vl.y), wfc[j+1], s);
        }
        ((float*)(smem + OFF_SPART))[tid] = s;
    }
    __syncthreads();
    if (tid < 64){
        const float* sp = (const float*)(smem + OFF_SPART);
        long long gb = baseb + tid;
        if (gb < Btot)
            out[gb] = sp[tid*4] + sp[tid*4+1] + sp[tid*4+2] + sp[tid*4+3] + bfc[0];
    }
}

// ============================================================================
extern "C" void kernel_launch(void* const* d_in, const int* in_sizes, int n_in,
                              void* d_out, int out_size)
{
    const float* x    = (const float*)d_in[0];
    const float* Wih0 = (const float*)d_in[1];
    const float* Whh0 = (const float*)d_in[2];
    const float* bih0 = (const float*)d_in[3];
    const float* bhh0 = (const float*)d_in[4];
    const float* WihS = (const float*)d_in[5];
    const float* WhhS = (const float*)d_in[6];
    const float* bihS = (const float*)d_in[7];
    const float* bhhS = (const float*)d_in[8];
    const float* Wfc  = (const float*)d_in[9];
    const float* bfc  = (const float*)d_in[10];
    float* out = (float*)d_out;

    int Btot = in_sizes[0] / 20;
    int grid = (Btot + MB - 1) / MB;

    cudaFuncSetAttribute(rnn_mma,
                         cudaFuncAttributeMaxDynamicSharedMemorySize, SMEM_BYTES);

    prep_weights<<<10, 256>>>(Wih0, Whh0, WihS, WhhS);
    rnn_mma<<<grid, NT, SMEM_BYTES>>>(x, bih0, bhh0, bihS, bhhS,
                                      Wfc, bfc, out, Btot);
}

// round 14
// speedup vs baseline: 2.5773x; 2.5773x over previous
#include <cuda_runtime.h>
#include <cuda_bf16.h>
#include <cstdint>

// ============================================================================
// RNNModel B=262144, F=5, T=4, H=128, L=5 — bf16 mma.sync split-precision v6.
// 3-term split (W=Wh+Wl, h=hh+hl; D = AhBh + AhBl + AlBh), ldmatrix fragment
// loads, 4 batch groups of 4 warps. v6 = R8 kernel (proven 2367us) with ONLY
// the packed cvt.rn.bf16x2 epilogue/x-staging swapped in (pure-ALU delta).
// Copy path restored verbatim: padded gmem mirrors, identity-offset cp.async
// (dst_off == src_off, 128B-aligned sectors -> full LDGSTS coalescing).
// ============================================================================

#define HDIM 128
#define TSEQ 4
#define MB   64
#define NT   512
#define NLAYER 5

#define HPW  68                  // padded row stride in u32 words (136 bf16, 272 B)
#define ROWB 272                 // bytes per padded row
#define W_HALF_BYTES 34816       // 128*272
#define H_TILE_BYTES 17408       // 64*272

// ---- SMEM byte offsets ----
#define OFF_H     0                       // 4t x (hi 17408 + lo 17408) = 139264
#define H_PAIR    34816
#define OFF_W     139264                  // Whi 34816 + Wlo 34816 = 69632
#define OFF_X     208896                  // 4t x (hi 2048 + lo 2048) = 16384
#define X_PAIR    4096
#define OFF_B2    225280                  // 128 fp32
#define OFF_WFC   225792                  // 128 fp32
#define OFF_SPART 226304                  // 256 fp32
#define SMEM_BYTES 227328

// ---- pre-split, PADDED weights (mirror of SMEM layout): slot 2l = W_ih(l),
// 2l+1 = W_hh(l). layout: [j][136] bf16 rows; cols >= real K zero-filled.
__device__ __align__(16) __nv_bfloat16 g_Whi[10][17408];
__device__ __align__(16) __nv_bfloat16 g_Wlo[10][17408];

__device__ __forceinline__ uint32_t smem_u32(const void* p){
    uint32_t a;
    asm("{ .reg .u64 t; cvta.to.shared.u64 t, %1; cvt.u32.u64 %0, t; }"
        : "=r"(a) : "l"(p));
    return a;
}

__device__ __forceinline__ void ldm4(uint32_t* r, uint32_t addr){
    asm volatile("ldmatrix.sync.aligned.m8n8.x4.shared.b16 {%0,%1,%2,%3}, [%4];"
        : "=r"(r[0]), "=r"(r[1]), "=r"(r[2]), "=r"(r[3]) : "r"(addr));
}

__device__ __forceinline__ void mma16816(float* c,
        uint32_t a0, uint32_t a1, uint32_t a2, uint32_t a3,
        uint32_t b0, uint32_t b1){
    asm volatile(
        "mma.sync.aligned.m16n8k16.row.col.f32.bf16.bf16.f32 "
        "{%0,%1,%2,%3}, {%4,%5,%6,%7}, {%8,%9}, {%0,%1,%2,%3};"
        : "+f"(c[0]), "+f"(c[1]), "+f"(c[2]), "+f"(c[3])
        : "r"(a0), "r"(a1), "r"(a2), "r"(a3), "r"(b0), "r"(b1));
}

#define GROUP_BAR(gid) \
    asm volatile("bar.sync %0, %1;" :: "r"((gid) + 1), "r"(128) : "memory")

__device__ __forceinline__ void cp_async16(uint32_t dst, const void* src){
    asm volatile("cp.async.cg.shared.global [%0], [%1], 16;"
                 :: "r"(dst), "l"(src) : "memory");
}
#define CP_ASYNC_COMMIT() asm volatile("cp.async.commit_group;" ::: "memory")
#define CP_ASYNC_WAIT()   asm volatile("cp.async.wait_group 0;" ::: "memory")

// accurate tanh (~1e-7 abs). NOT tanh.approx (6e-4 would compound over 20 steps).
__device__ __forceinline__ float fast_tanh(float x){
    float ax = fabsf(x);
    float e  = __expf(-2.0f * ax);
    float r  = __fdividef(1.0f - e, 1.0f + e);
    return copysignf(r, x);
}

// ============================================================================
// Prep: split all 10 weight matrices into bf16 hi/lo, padded [j][136] rows.
// ============================================================================
__global__ void prep_weights(const float* __restrict__ Wih0,
                             const float* __restrict__ Whh0,
                             const float* __restrict__ WihS,
                             const float* __restrict__ WhhS){
    int slot = blockIdx.x;
    for (int idx = threadIdx.x; idx < 17408; idx += blockDim.x){
        int j = idx / 136, k = idx % 136;
        float w = 0.0f;
        if (slot == 0)      { if (k < 5)   w = Wih0[j*5 + k]; }
        else if (slot == 1) { if (k < 128) w = Whh0[j*128 + k]; }
        else if (slot & 1)  { if (k < 128) w = WhhS[((slot>>1)-1)*16384 + j*128 + k]; }
        else                { if (k < 128) w = WihS[((slot>>1)-1)*16384 + j*128 + k]; }
        __nv_bfloat16 hi = __float2bfloat16(w);
        __nv_bfloat16 lo = __float2bfloat16(w - __bfloat162float(hi));
        g_Whi[slot][idx] = hi;
        g_Wlo[slot][idx] = lo;
    }
}

// async copy one matrix (hi+lo) into the SMEM W region — IDENTITY offsets
// (dst_off == src_off), fully contiguous and 128B-sector aligned both sides.
__device__ __forceinline__ void copyW_async(int slot, uint32_t sbW, int tid){
    const char* gh = (const char*)g_Whi[slot];
    const char* gl = (const char*)g_Wlo[slot];
    #pragma unroll 5
    for (int i = tid; i < 2176; i += NT){
        cp_async16(sbW + i*16,                 gh + i*16);
        cp_async16(sbW + W_HALF_BYTES + i*16,  gl + i*16);
    }
    CP_ASYNC_COMMIT();
}

// epilogue for one timestep: tanh, split hi/lo (packed cvt.rn — identical
// rounding to __float2bfloat16), store to h tiles
__device__ __forceinline__ void epi_store(const float* ct,
        uint32_t* hh, uint32_t* hl, int baseW){
    #pragma unroll
    for (int nf = 0; nf < 4; nf++){
        #pragma unroll
        for (int p = 0; p < 2; p++){
            float h0 = fast_tanh(ct[nf*4 + 2*p]);
            float h1 = fast_tanh(ct[nf*4 + 2*p + 1]);
            uint32_t ph;
            asm("cvt.rn.bf16x2.f32 %0, %1, %2;" : "=r"(ph) : "f"(h1), "f"(h0));
            float f0 = __uint_as_float(ph << 16);
            float f1 = __uint_as_float(ph & 0xffff0000u);
            uint32_t pl;
            asm("cvt.rn.bf16x2.f32 %0, %1, %2;" : "=r"(pl) : "f"(h1 - f1), "f"(h0 - f0));
            int widx = baseW + p*(8*HPW) + nf*4;
            hh[widx] = ph;
            hl[widx] = pl;
        }
    }
}

// ============================================================================
__global__ void __launch_bounds__(NT)
rnn_mma(const float* __restrict__ x,
        const float* __restrict__ bih0, const float* __restrict__ bhh0,
        const float* __restrict__ bihS, const float* __restrict__ bhhS,
        const float* __restrict__ Wfc,  const float* __restrict__ bfc,
        float* __restrict__ out, int Btot)
{
    extern __shared__ __align__(16) char smem[];
    const uint32_t sb = smem_u32(smem);
    const int tid  = threadIdx.x;
    const int wid  = tid >> 5, lane = tid & 31;
    const int g    = lane >> 2, c = lane & 3;
    const int grp  = wid >> 2;               // batch group 0..3 (spans all SMSPs)
    const int m0   = grp * 16;               // group's 16 batch rows
    const int n0   = (wid & 3) * 32;         // warp's hidden-col base
    const long long baseb = (long long)blockIdx.x * MB;

    float* b2  = (float*)(smem + OFF_B2);
    float* wfc = (float*)(smem + OFF_WFC);

    // ---- per-lane ldmatrix byte offsets ----
    const int aRow = m0 + (lane & 7) + ((lane >> 3) & 1) * 8;
    const int aK8  = (lane >> 4) * 8;
    const uint32_t aOff = (uint32_t)(aRow * ROWB + aK8 * 2);
    const int bRow = (lane & 7) + (lane >> 4) * 8;
    const int bK8  = ((lane >> 3) & 1) * 8;
    const uint32_t bOff0 = (uint32_t)((n0 + bRow) * ROWB + bK8 * 2);
    const uint32_t bOff1 = (uint32_t)((n0 + 16 + bRow) * ROWB + bK8 * 2);
    const int baseW = (m0 + g) * HPW + (n0 >> 1) + c;   // epilogue store base

    // ---- stage wfc + x tiles (bf16 hi/lo split, [64][8 words]) ----
    if (tid < 128) wfc[tid] = Wfc[tid];
    if (tid < 256){
        int b = tid >> 2, t = tid & 3;
        long long gb = baseb + b;
        float xv[5];
        #pragma unroll
        for (int f = 0; f < 5; f++)
            xv[f] = (gb < Btot) ? x[gb*20 + f*4 + t] : 0.0f;
        uint32_t* xh = (uint32_t*)(smem + OFF_X + t*X_PAIR);
        uint32_t* xl = xh + 512;
        #pragma unroll
        for (int w = 0; w < 8; w++){
            float v0 = (2*w   < 5) ? xv[2*w]   : 0.0f;
            float v1 = (2*w+1 < 5) ? xv[2*w+1] : 0.0f;
            uint32_t ph;
            asm("cvt.rn.bf16x2.f32 %0, %1, %2;" : "=r"(ph) : "f"(v1), "f"(v0));
            float f0 = __uint_as_float(ph << 16);
            float f1 = __uint_as_float(ph & 0xffff0000u);
            uint32_t pl;
            asm("cvt.rn.bf16x2.f32 %0, %1, %2;" : "=r"(pl) : "f"(v1 - f1), "f"(v0 - f0));
            xh[b*8 + w] = ph;
            xl[b*8 + w] = pl;
        }
    }

    float acc[64];                           // [t][nf][4]
    const uint32_t whAddr = sb + OFF_W;
    const uint32_t wlAddr = sb + OFF_W + W_HALF_BYTES;
    const uint32_t* whW = (const uint32_t*)(smem + OFF_W);
    const uint32_t* wlW = whW + (W_HALF_BYTES >> 2);

    #pragma unroll 1
    for (int l = 0; l < NLAYER; l++){
        __syncthreads();                     // all reads of previous W done
        copyW_async(2*l, sb + OFF_W, tid);
        if (tid < 128)
            b2[tid] = (l == 0) ? bih0[tid] + bhh0[tid]
                               : bihS[(l-1)*128 + tid] + bhhS[(l-1)*128 + tid];
        CP_ASYNC_WAIT();
        __syncthreads();

        // ---- init acc with bias ----
        #pragma unroll
        for (int nf = 0; nf < 4; nf++){
            float bv0 = b2[n0 + nf*8 + c*2];
            float bv1 = b2[n0 + nf*8 + c*2 + 1];
            #pragma unroll
            for (int t = 0; t < 4; t++){
                float* cc = &acc[(t*4 + nf)*4];
                cc[0] = bv0; cc[1] = bv1; cc[2] = bv0; cc[3] = bv1;
            }
        }

        // ---- pass A: acc[t] += Wih . h_prev[t] (no barriers needed) ----
        if (l == 0){
            // single K=16 step from x tiles (scalar LDS; tiny)
            uint32_t bh[8], bl[8];
            #pragma unroll
            for (int nf = 0; nf < 4; nf++){
                int jw = (n0 + nf*8 + g)*HPW + c;
                bh[nf*2]   = whW[jw]; bh[nf*2+1] = whW[jw + 4];
                bl[nf*2]   = wlW[jw]; bl[nf*2+1] = wlW[jw + 4];
            }
            #pragma unroll
            for (int t = 0; t < 4; t++){
                const uint32_t* xh = (const uint32_t*)(smem + OFF_X + t*X_PAIR);
                const uint32_t* xl = xh + 512;
                int rw = (m0 + g)*8 + c;
                uint32_t ah0 = xh[rw], ah1 = xh[rw + 64];
                uint32_t ah2 = xh[rw + 4], ah3 = xh[rw + 68];
                uint32_t al0 = xl[rw], al1 = xl[rw + 64];
                uint32_t al2 = xl[rw + 4], al3 = xl[rw + 68];
                float* ct = &acc[t*16];
                #pragma unroll
                for (int nf = 0; nf < 4; nf++)
                    mma16816(ct + nf*4, ah0,ah1,ah2,ah3, bh[nf*2], bh[nf*2+1]);
                #pragma unroll
                for (int nf = 0; nf < 4; nf++)
                    mma16816(ct + nf*4, ah0,ah1,ah2,ah3, bl[nf*2], bl[nf*2+1]);
                #pragma unroll
                for (int nf = 0; nf < 4; nf++)
                    mma16816(ct + nf*4, al0,al1,al2,al3, bh[nf*2], bh[nf*2+1]);
            }
        } else {
            #pragma unroll 1
            for (int kk = 0; kk < 8; kk++){
                uint32_t kb = kk * 32;       // 16 bf16 = 32 bytes per k-chunk
                uint32_t bh[8], bl[8];
                ldm4(bh,     whAddr + bOff0 + kb);
                ldm4(bh + 4, whAddr + bOff1 + kb);
                ldm4(bl,     wlAddr + bOff0 + kb);
                ldm4(bl + 4, wlAddr + bOff1 + kb);
                #pragma unroll
                for (int t = 0; t < 4; t++){
                    uint32_t hAddr = sb + OFF_H + t*H_PAIR + aOff + kb;
                    uint32_t ah[4], al[4];
                    ldm4(ah, hAddr);
                    ldm4(al, hAddr + H_TILE_BYTES);
                    float* ct = &acc[t*16];
                    #pragma unroll
                    for (int nf = 0; nf < 4; nf++)
                        mma16816(ct + nf*4, ah[0],ah[1],ah[2],ah[3], bh[nf*2], bh[nf*2+1]);
                    #pragma unroll
                    for (int nf = 0; nf < 4; nf++)
                        mma16816(ct + nf*4, ah[0],ah[1],ah[2],ah[3], bl[nf*2], bl[nf*2+1]);
                    #pragma unroll
                    for (int nf = 0; nf < 4; nf++)
                        mma16816(ct + nf*4, al[0],al[1],al[2],al[3], bh[nf*2], bh[nf*2+1]);
                }
            }
        }

        // ---- swap W region to W_hh(l) (sequential, as in proven v3) ----
        __syncthreads();                     // pass-A reads of Wih done
        copyW_async(2*l + 1, sb + OFF_W, tid);
        CP_ASYNC_WAIT();
        __syncthreads();

        // ---- pass B: sequential timesteps; 128-thread group barriers ----
        #pragma unroll
        for (int t = 0; t < 4; t++){
            if (t > 0){
                float* ct = &acc[t*16];
                uint32_t hBase = sb + OFF_H + (t-1)*H_PAIR;
                #pragma unroll 1
                for (int kk = 0; kk < 8; kk++){
                    uint32_t kb = kk * 32;
                    uint32_t bh[8], bl[8], ah[4], al[4];
                    ldm4(bh,     whAddr + bOff0 + kb);
                    ldm4(bh + 4, whAddr + bOff1 + kb);
                    ldm4(bl,     wlAddr + bOff0 + kb);
                    ldm4(bl + 4, wlAddr + bOff1 + kb);
                    ldm4(ah, hBase + aOff + kb);
                    ldm4(al, hBase + aOff + kb + H_TILE_BYTES);
                    #pragma unroll
                    for (int nf = 0; nf < 4; nf++)
                        mma16816(ct + nf*4, ah[0],ah[1],ah[2],ah[3], bh[nf*2], bh[nf*2+1]);
                    #pragma unroll
                    for (int nf = 0; nf < 4; nf++)
                        mma16816(ct + nf*4, ah[0],ah[1],ah[2],ah[3], bl[nf*2], bl[nf*2+1]);
                    #pragma unroll
                    for (int nf = 0; nf < 4; nf++)
                        mma16816(ct + nf*4, al[0],al[1],al[2],al[3], bh[nf*2], bh[nf*2+1]);
                }
            }
            // epilogue: h_t = tanh(acc[t]); split; store (in-place)
            uint32_t* hh = (uint32_t*)(smem + OFF_H + t*H_PAIR);
            epi_store(&acc[t*16], hh, hh + (H_TILE_BYTES >> 2), baseW);
            if (t < 3) GROUP_BAR(grp);       // h[t] visible within this batch group
            // t==3: next layer-top __syncthreads (or head's) provides ordering
        }
    }

    __syncthreads();                         // all groups' h[3] complete

    // ---- head: out[b] = dot(h3[b], wfc) + bfc ----
    if (tid < 256){
        int b = tid >> 2, q = tid & 3;
        const uint32_t* hh = (const uint32_t*)(smem + OFF_H + 3*H_PAIR);
        const uint32_t* hl = hh + (H_TILE_BYTES >> 2);
        float s = 0.0f;
        #pragma unroll
        for (int w = 0; w < 16; w++){
            int widx = b*HPW + q*16 + w;
            uint32_t uh = hh[widx], ul = hl[widx];
            __nv_bfloat162 vh = *(__nv_bfloat162*)&uh;
            __nv_bfloat162 vl = *(__nv_bfloat162*)&ul;
            int j = q*32 + 2*w;
            s = fmaf(__bfloat162float(vh.x) + __bfloat162float(vl.x), wfc[j],   s);
            s = fmaf(__bfloat162float(vh.y) + __bfloat162float(vl.y), wfc[j+1], s);
        }
        ((float*)(smem + OFF_SPART))[tid] = s;
    }
    __syncthreads();
    if (tid < 64){
        const float* sp = (const float*)(smem + OFF_SPART);
        long long gb = baseb + tid;
        if (gb < Btot)
            out[gb] = sp[tid*4] + sp[tid*4+1] + sp[tid*4+2] + sp[tid*4+3] + bfc[0];
    }
}

// ============================================================================
extern "C" void kernel_launch(void* const* d_in, const int* in_sizes, int n_in,
                              void* d_out, int out_size)
{
    const float* x    = (const float*)d_in[0];
    const float* Wih0 = (const float*)d_in[1];
    const float* Whh0 = (const float*)d_in[2];
    const float* bih0 = (const float*)d_in[3];
    const float* bhh0 = (const float*)d_in[4];
    const float* WihS = (const float*)d_in[5];
    const float* WhhS = (const float*)d_in[6];
    const float* bihS = (const float*)d_in[7];
    const float* bhhS = (const float*)d_in[8];
    const float* Wfc  = (const float*)d_in[9];
    const float* bfc  = (const float*)d_in[10];
    float* out = (float*)d_out;

    int Btot = in_sizes[0] / 20;
    int grid = (Btot + MB - 1) / MB;

    cudaFuncSetAttribute(rnn_mma,
                         cudaFuncAttributeMaxDynamicSharedMemorySize, SMEM_BYTES);

    prep_weights<<<10, 256>>>(Wih0, Whh0, WihS, WhhS);
    rnn_mma<<<grid, NT, SMEM_BYTES>>>(x, bih0, bhh0, bihS, bhhS,
                                      Wfc, bfc, out, Btot);
}